// round 1
// baseline (speedup 1.0000x reference)
#include <cuda_runtime.h>
#include <math.h>

// Problem constants
#define B_    4096
#define N_    32
#define H_    8
#define D_    64
#define HID   512
#define M_TOT (B_ * N_)             // 131072
#define OUT_OFF ((size_t)M_TOT * HID)   // 67108864 floats (output region size)
#define ATTN_SIZE ((size_t)B_ * H_ * N_ * N_)  // 33554432

// Scratch (device globals: allocation-guard safe)
__device__ float g_qkv[(size_t)M_TOT * 3 * HID];   // [B*N, 1536]  (q|k|v per row)
__device__ float g_ctx[(size_t)M_TOT * HID];       // [B*N, 512]
__device__ unsigned g_mask_bits[N_];               // 32-bit row masks

// ---------------------------------------------------------------------------
// Mask normalizer: sparse_mask arrives as bool(1B) / int32 / float32 — detect.
// Diagonal is guaranteed true, so the 1-byte interpretation passes the
// diagonal test iff the data really is 1-byte. The 1-byte probe touches at
// most byte 1023, which is in-bounds for every candidate layout.
// ---------------------------------------------------------------------------
__global__ void normalize_mask_kernel(const void* maskp) {
    int i = threadIdx.x;  // 0..31
    const unsigned char* m8 = (const unsigned char*)maskp;
    unsigned diag_ok = __ballot_sync(0xffffffffu, m8[i * 33] != 0);
    unsigned bits = 0;
    if (diag_ok == 0xffffffffu) {
        // genuine 1-byte bool layout
        for (int j = 0; j < 32; j++)
            bits |= (unsigned)(m8[i * 32 + j] != 0) << j;
    } else {
        // 4-byte layout (int32 or float32: nonzero pattern works for both)
        const int* m32 = (const int*)maskp;
        for (int j = 0; j < 32; j++)
            bits |= (unsigned)(m32[i * 32 + j] != 0) << j;
    }
    g_mask_bits[i] = bits;
}

// ---------------------------------------------------------------------------
// SGEMM (TN): C[M,N] = A[M,K] @ W[N,K]^T + bias[N]
// 128x128 block tile, BK=8, 256 threads, 8x8 microtile, float4 loads.
// Requires M%128==0, N%128==0, K%8==0 (true for all call sites).
// ---------------------------------------------------------------------------
__global__ __launch_bounds__(256) void sgemm_tn(
    const float* __restrict__ A, const float* __restrict__ W,
    const float* __restrict__ bias, float* __restrict__ C,
    int M, int N, int K)
{
    __shared__ float As[8][128];
    __shared__ float Bs[8][128];

    const int bm = blockIdx.y * 128;
    const int bn = blockIdx.x * 128;
    const int tid = threadIdx.x;

    const int lrow = tid >> 1;          // 0..127
    const int lcol = (tid & 1) * 4;     // 0 or 4
    const float* Ap = A + (size_t)(bm + lrow) * K + lcol;
    const float* Wp = W + (size_t)(bn + lrow) * K + lcol;

    const int tm = (tid >> 4) * 8;      // 0..120
    const int tn = (tid & 15) * 8;      // 0..120

    float acc[8][8];
    #pragma unroll
    for (int i = 0; i < 8; i++)
        #pragma unroll
        for (int j = 0; j < 8; j++) acc[i][j] = 0.f;

    for (int k0 = 0; k0 < K; k0 += 8) {
        float4 a4 = *(const float4*)(Ap + k0);
        float4 w4 = *(const float4*)(Wp + k0);
        __syncthreads();   // previous iteration's compute must be done
        As[lcol + 0][lrow] = a4.x; As[lcol + 1][lrow] = a4.y;
        As[lcol + 2][lrow] = a4.z; As[lcol + 3][lrow] = a4.w;
        Bs[lcol + 0][lrow] = w4.x; Bs[lcol + 1][lrow] = w4.y;
        Bs[lcol + 2][lrow] = w4.z; Bs[lcol + 3][lrow] = w4.w;
        __syncthreads();
        #pragma unroll
        for (int kk = 0; kk < 8; kk++) {
            float a[8], b[8];
            *(float4*)(a + 0) = *(const float4*)&As[kk][tm];
            *(float4*)(a + 4) = *(const float4*)&As[kk][tm + 4];
            *(float4*)(b + 0) = *(const float4*)&Bs[kk][tn];
            *(float4*)(b + 4) = *(const float4*)&Bs[kk][tn + 4];
            #pragma unroll
            for (int i = 0; i < 8; i++)
                #pragma unroll
                for (int j = 0; j < 8; j++)
                    acc[i][j] += a[i] * b[j];
        }
    }

    float bb[8];
    #pragma unroll
    for (int j = 0; j < 8; j++) bb[j] = bias[bn + tn + j];
    #pragma unroll
    for (int i = 0; i < 8; i++) {
        float* Crow = C + (size_t)(bm + tm + i) * N + bn + tn;
        float4 v0, v1;
        v0.x = acc[i][0] + bb[0]; v0.y = acc[i][1] + bb[1];
        v0.z = acc[i][2] + bb[2]; v0.w = acc[i][3] + bb[3];
        v1.x = acc[i][4] + bb[4]; v1.y = acc[i][5] + bb[5];
        v1.z = acc[i][6] + bb[6]; v1.w = acc[i][7] + bb[7];
        *(float4*)(Crow + 0) = v0;
        *(float4*)(Crow + 4) = v1;
    }
}

// ---------------------------------------------------------------------------
// Attention: one block per batch b, one warp per head h.
// q,k,v tiles are [32,64]; smem stride 65 => conflict-free.
// Per warp smem: bufA (q -> attn probs), bufB (k -> v): 2*2080 floats.
// ---------------------------------------------------------------------------
#define WBUF 2080                         // 32*65
#define ATTN_SMEM (8 * 2 * WBUF * 4)      // 133120 bytes

__global__ __launch_bounds__(256) void attn_kernel(
    const float* __restrict__ qkv,
    float* __restrict__ attn_out,         // may be null (skip attn output)
    float* __restrict__ ctx_out)
{
    extern __shared__ float sh[];
    const int b = blockIdx.x;
    const int warp = threadIdx.x >> 5;    // head
    const int lane = threadIdx.x & 31;

    float* bufA = sh + warp * (2 * WBUF);
    float* bufB = bufA + WBUF;

    const float* base = qkv + (size_t)b * 32 * 1536 + warp * 64;

    // load q into bufA, k into bufB (coalesced: 128B per row-half)
    #pragma unroll 4
    for (int r = 0; r < 32; r++) {
        const float* row = base + (size_t)r * 1536;
        bufA[r * 65 + lane]      = row[lane];
        bufA[r * 65 + lane + 32] = row[lane + 32];
        bufB[r * 65 + lane]      = row[512 + lane];
        bufB[r * 65 + lane + 32] = row[512 + lane + 32];
    }
    __syncwarp();

    // scores: lane i owns row i
    const int i = lane;
    float qa[64];
    #pragma unroll
    for (int d = 0; d < 64; d++) qa[d] = bufA[i * 65 + d];

    const unsigned bits = g_mask_bits[i];
    float s[32];
    #pragma unroll 4
    for (int j = 0; j < 32; j++) {
        float acc = 0.f;
        #pragma unroll
        for (int d = 0; d < 64; d++) acc += qa[d] * bufB[j * 65 + d];
        s[j] = ((bits >> j) & 1u) ? acc * 0.125f : -1e9f;
    }

    // softmax (exact jax semantics: masked entries underflow to 0)
    float mx = -1e30f;
    #pragma unroll
    for (int j = 0; j < 32; j++) mx = fmaxf(mx, s[j]);
    float sum = 0.f;
    #pragma unroll
    for (int j = 0; j < 32; j++) { s[j] = expf(s[j] - mx); sum += s[j]; }
    const float inv = 1.f / sum;
    #pragma unroll
    for (int j = 0; j < 32; j++) bufA[i * 65 + j] = s[j] * inv;  // p row i (q row i dead)
    __syncwarp();   // all p rows written; all k reads done

    // attn output (coalesced via smem)
    if (attn_out) {
        float* ao = attn_out + ((size_t)(b * 8 + warp) * 32) * 32;
        #pragma unroll 4
        for (int r = 0; r < 32; r++) ao[r * 32 + lane] = bufA[r * 65 + lane];
    }

    // overwrite bufB with v
    #pragma unroll 4
    for (int r = 0; r < 32; r++) {
        const float* row = base + (size_t)r * 1536 + 1024;
        bufB[r * 65 + lane]      = row[lane];
        bufB[r * 65 + lane + 32] = row[lane + 32];
    }
    __syncwarp();

    // ctx[r, d] = sum_j p[r,j] * v[j,d]; lane owns columns d=lane, lane+32
    #pragma unroll 2
    for (int r = 0; r < 32; r++) {
        float c0 = 0.f, c1 = 0.f;
        #pragma unroll
        for (int j = 0; j < 32; j++) {
            float p = bufA[r * 65 + j];
            c0 += p * bufB[j * 65 + lane];
            c1 += p * bufB[j * 65 + lane + 32];
        }
        float* co = ctx_out + (size_t)(b * 32 + r) * HID + warp * 64;
        co[lane]      = c0;
        co[lane + 32] = c1;
    }
}

// ---------------------------------------------------------------------------
extern "C" void kernel_launch(void* const* d_in, const int* in_sizes, int n_in,
                              void* d_out, int out_size)
{
    const float* X    = (const float*)d_in[0];  // [B,N,HID]
    const void*  mask = d_in[1];                // [N,N] bool-ish
    const float* Wqkv = (const float*)d_in[2];  // [1536,512]
    const float* bqkv = (const float*)d_in[3];  // [1536]
    const float* Wo   = (const float*)d_in[4];  // [512,512]
    const float* bo   = (const float*)d_in[5];  // [512]
    float* out = (float*)d_out;

    cudaFuncSetAttribute(attn_kernel,
                         cudaFuncAttributeMaxDynamicSharedMemorySize, ATTN_SMEM);

    float* qkv_p = nullptr;
    float* ctx_p = nullptr;
    cudaGetSymbolAddress((void**)&qkv_p, g_qkv);
    cudaGetSymbolAddress((void**)&ctx_p, g_ctx);

    // Only write attn if the output buffer holds both tensors
    float* attn_p = ((size_t)out_size >= OUT_OFF + ATTN_SIZE) ? out + OUT_OFF
                                                              : nullptr;

    normalize_mask_kernel<<<1, 32>>>(mask);

    dim3 g1(3 * HID / 128, M_TOT / 128);   // (12, 1024)
    sgemm_tn<<<g1, 256>>>(X, Wqkv, bqkv, qkv_p, M_TOT, 3 * HID, HID);

    attn_kernel<<<B_, 256, ATTN_SMEM>>>(qkv_p, attn_p, ctx_p);

    dim3 g2(HID / 128, M_TOT / 128);       // (4, 1024)
    sgemm_tn<<<g2, 256>>>(ctx_p, Wo, bo, out, M_TOT, HID, HID);
}

// round 2
// speedup vs baseline: 2.9131x; 2.9131x over previous
#include <cuda_runtime.h>
#include <math.h>
#include <stdint.h>

// Problem constants
#define B_    4096
#define N_    32
#define H_    8
#define HID   512
#define M_TOT (B_ * N_)                         // 131072
#define OUT_OFF ((size_t)M_TOT * HID)           // 67108864 floats
#define ATTN_SIZE ((size_t)B_ * H_ * N_ * N_)   // 33554432

// Scratch (device globals: allocation-guard safe)
__device__ float g_qkv[(size_t)M_TOT * 3 * HID];     // [B*N, 1536]
__device__ float g_ctx[(size_t)M_TOT * HID];         // [B*N, 512] (tf32-rounded)
__device__ float g_xt[(size_t)M_TOT * HID];          // tf32-rounded X
__device__ float g_wqkv[(size_t)3 * HID * HID];      // tf32-rounded Wqkv
__device__ float g_wo[(size_t)HID * HID];            // tf32-rounded Wo
__device__ unsigned g_mask_bits[N_];

// ---------------------------------------------------------------------------
// Mask normalizer (dtype-agnostic: 1-byte bool vs 4-byte int/float)
// ---------------------------------------------------------------------------
__global__ void normalize_mask_kernel(const void* maskp) {
    int i = threadIdx.x;  // 0..31
    const unsigned char* m8 = (const unsigned char*)maskp;
    unsigned diag_ok = __ballot_sync(0xffffffffu, m8[i * 33] != 0);
    unsigned bits = 0;
    if (diag_ok == 0xffffffffu) {
        for (int j = 0; j < 32; j++)
            bits |= (unsigned)(m8[i * 32 + j] != 0) << j;
    } else {
        const int* m32 = (const int*)maskp;
        for (int j = 0; j < 32; j++)
            bits |= (unsigned)(m32[i * 32 + j] != 0) << j;
    }
    g_mask_bits[i] = bits;
}

// ---------------------------------------------------------------------------
// Round fp32 -> tf32 (rna) elementwise, float4 vectorized.
// ---------------------------------------------------------------------------
__device__ __forceinline__ float to_tf32(float x) {
    uint32_t u;
    asm("cvt.rna.tf32.f32 %0, %1;" : "=r"(u) : "f"(x));
    return __uint_as_float(u);
}

__global__ void round_tf32_kernel(const float* __restrict__ in,
                                  float* __restrict__ out, int n4) {
    int i = blockIdx.x * blockDim.x + threadIdx.x;
    if (i >= n4) return;
    float4 v = ((const float4*)in)[i];
    v.x = to_tf32(v.x); v.y = to_tf32(v.y);
    v.z = to_tf32(v.z); v.w = to_tf32(v.w);
    ((float4*)out)[i] = v;
}

// ---------------------------------------------------------------------------
// TF32 tensor-core GEMM (TN): C[M,N] = A[M,K] @ W[N,K]^T + bias[N]
// Inputs must already be tf32-rounded. 128x128x32 tile, 256 threads,
// 8 warps x (64x32) warp tiles, m16n8k8 mma, cp.async double buffering.
// Requires M%128==0, N%128==0, K%32==0, K/32 >= 2.
// ---------------------------------------------------------------------------
#define BM 128
#define BN 128
#define BK 32
#define PAD 36
#define TILE_F ((BM + BN) * PAD)            // 9216 floats per stage
#define GEMM_SMEM (2 * TILE_F * 4)          // 73728 bytes

__device__ __forceinline__ void cp16(uint32_t dst, const void* src) {
    asm volatile("cp.async.cg.shared.global [%0], [%1], 16;\n"
                 :: "r"(dst), "l"(src));
}

__global__ __launch_bounds__(256, 2) void mma_tn(
    const float* __restrict__ A, const float* __restrict__ W,
    const float* __restrict__ bias, float* __restrict__ C,
    int M, int N, int K)
{
    extern __shared__ float sh[];
    const int tid = threadIdx.x;
    const int bm = blockIdx.y * BM;
    const int bn = blockIdx.x * BN;

    const uint32_t sbase = (uint32_t)__cvta_generic_to_shared(sh);

    // Loader mapping: each thread copies 4x16B of A and 4x16B of B per tile.
    const int lrow = tid >> 3;          // 0..31
    const int lk = (tid & 7) * 4;       // 0..28
    const float* Ag = A + (size_t)(bm + lrow) * K + lk;
    const float* Wg = W + (size_t)(bn + lrow) * K + lk;

    auto issue = [&](int k0, int s) {
        uint32_t abuf = sbase + (uint32_t)(s * TILE_F) * 4u;
        uint32_t bbuf = abuf + BM * PAD * 4u;
        #pragma unroll
        for (int i = 0; i < 4; i++) {
            int m = lrow + i * 32;
            cp16(abuf + (uint32_t)(m * PAD + lk) * 4u, Ag + (size_t)(i * 32) * K + k0);
            cp16(bbuf + (uint32_t)(m * PAD + lk) * 4u, Wg + (size_t)(i * 32) * K + k0);
        }
        asm volatile("cp.async.commit_group;\n");
    };

    const int warp = tid >> 5, lane = tid & 31;
    const int wm = (warp >> 2) * 64;    // 0 or 64
    const int wn = (warp & 3) * 32;     // 0,32,64,96
    const int qr = lane >> 2;           // 0..7
    const int qc = lane & 3;            // 0..3

    float acc[4][4][4];
    #pragma unroll
    for (int a = 0; a < 4; a++)
        #pragma unroll
        for (int b = 0; b < 4; b++)
            #pragma unroll
            for (int c = 0; c < 4; c++) acc[a][b][c] = 0.f;

    const int nIter = K / BK;
    issue(0, 0);
    issue(BK, 1);

    for (int it = 0; it < nIter; it++) {
        if (it + 1 < nIter) asm volatile("cp.async.wait_group 1;\n");
        else                asm volatile("cp.async.wait_group 0;\n");
        __syncthreads();

        const uint32_t* Au = (const uint32_t*)(sh + (it & 1) * TILE_F);
        const uint32_t* Bu = Au + BM * PAD;

        #pragma unroll
        for (int ks = 0; ks < 4; ks++) {
            uint32_t af[4][4], bf[4][2];
            const int kk = ks * 8 + qc;
            #pragma unroll
            for (int mt = 0; mt < 4; mt++) {
                int base = (wm + mt * 16 + qr) * PAD + kk;
                af[mt][0] = Au[base];
                af[mt][1] = Au[base + 8 * PAD];
                af[mt][2] = Au[base + 4];
                af[mt][3] = Au[base + 8 * PAD + 4];
            }
            #pragma unroll
            for (int nt = 0; nt < 4; nt++) {
                int base = (wn + nt * 8 + qr) * PAD + kk;
                bf[nt][0] = Bu[base];
                bf[nt][1] = Bu[base + 4];
            }
            #pragma unroll
            for (int mt = 0; mt < 4; mt++)
                #pragma unroll
                for (int nt = 0; nt < 4; nt++)
                    asm volatile(
                        "mma.sync.aligned.m16n8k8.row.col.f32.tf32.tf32.f32 "
                        "{%0,%1,%2,%3}, {%4,%5,%6,%7}, {%8,%9}, {%0,%1,%2,%3};\n"
                        : "+f"(acc[mt][nt][0]), "+f"(acc[mt][nt][1]),
                          "+f"(acc[mt][nt][2]), "+f"(acc[mt][nt][3])
                        : "r"(af[mt][0]), "r"(af[mt][1]),
                          "r"(af[mt][2]), "r"(af[mt][3]),
                          "r"(bf[nt][0]), "r"(bf[nt][1]));
        }
        __syncthreads();
        if (it + 2 < nIter) issue((it + 2) * BK, it & 1);
    }

    // Epilogue: bias add + float2 stores
    #pragma unroll
    for (int nt = 0; nt < 4; nt++) {
        const int col = bn + wn + nt * 8 + qc * 2;
        const float2 bv = *(const float2*)(bias + col);
        #pragma unroll
        for (int mt = 0; mt < 4; mt++) {
            const int row = bm + wm + mt * 16 + qr;
            float2 v0 = { acc[mt][nt][0] + bv.x, acc[mt][nt][1] + bv.y };
            float2 v1 = { acc[mt][nt][2] + bv.x, acc[mt][nt][3] + bv.y };
            *(float2*)(C + (size_t)row * N + col) = v0;
            *(float2*)(C + (size_t)(row + 8) * N + col) = v1;
        }
    }
}

// ---------------------------------------------------------------------------
// Attention: one block per batch b, one warp per head h. fp32 exact.
// ctx output is tf32-rounded (consumed by the TF32 out-proj GEMM).
// ---------------------------------------------------------------------------
#define WBUF 2080                         // 32*65
#define ATTN_SMEM (8 * 2 * WBUF * 4)      // 133120 bytes

__global__ __launch_bounds__(256) void attn_kernel(
    const float* __restrict__ qkv,
    float* __restrict__ attn_out,
    float* __restrict__ ctx_out)
{
    extern __shared__ float sh[];
    const int b = blockIdx.x;
    const int warp = threadIdx.x >> 5;    // head
    const int lane = threadIdx.x & 31;

    float* bufA = sh + warp * (2 * WBUF);
    float* bufB = bufA + WBUF;

    const float* base = qkv + (size_t)b * 32 * 1536 + warp * 64;

    #pragma unroll 4
    for (int r = 0; r < 32; r++) {
        const float* row = base + (size_t)r * 1536;
        bufA[r * 65 + lane]      = row[lane];
        bufA[r * 65 + lane + 32] = row[lane + 32];
        bufB[r * 65 + lane]      = row[512 + lane];
        bufB[r * 65 + lane + 32] = row[512 + lane + 32];
    }
    __syncwarp();

    const int i = lane;
    float qa[64];
    #pragma unroll
    for (int d = 0; d < 64; d++) qa[d] = bufA[i * 65 + d];

    const unsigned bits = g_mask_bits[i];
    float s[32];
    #pragma unroll 4
    for (int j = 0; j < 32; j++) {
        float acc = 0.f;
        #pragma unroll
        for (int d = 0; d < 64; d++) acc += qa[d] * bufB[j * 65 + d];
        s[j] = ((bits >> j) & 1u) ? acc * 0.125f : -1e9f;
    }

    float mx = -1e30f;
    #pragma unroll
    for (int j = 0; j < 32; j++) mx = fmaxf(mx, s[j]);
    float sum = 0.f;
    #pragma unroll
    for (int j = 0; j < 32; j++) { s[j] = expf(s[j] - mx); sum += s[j]; }
    const float inv = 1.f / sum;
    #pragma unroll
    for (int j = 0; j < 32; j++) bufA[i * 65 + j] = s[j] * inv;
    __syncwarp();

    if (attn_out) {
        float* ao = attn_out + ((size_t)(b * 8 + warp) * 32) * 32;
        #pragma unroll 4
        for (int r = 0; r < 32; r++) ao[r * 32 + lane] = bufA[r * 65 + lane];
    }

    #pragma unroll 4
    for (int r = 0; r < 32; r++) {
        const float* row = base + (size_t)r * 1536 + 1024;
        bufB[r * 65 + lane]      = row[lane];
        bufB[r * 65 + lane + 32] = row[lane + 32];
    }
    __syncwarp();

    #pragma unroll 2
    for (int r = 0; r < 32; r++) {
        float c0 = 0.f, c1 = 0.f;
        #pragma unroll
        for (int j = 0; j < 32; j++) {
            float p = bufA[r * 65 + j];
            c0 += p * bufB[j * 65 + lane];
            c1 += p * bufB[j * 65 + lane + 32];
        }
        float* co = ctx_out + (size_t)(b * 32 + r) * HID + warp * 64;
        co[lane]      = to_tf32(c0);
        co[lane + 32] = to_tf32(c1);
    }
}

// ---------------------------------------------------------------------------
extern "C" void kernel_launch(void* const* d_in, const int* in_sizes, int n_in,
                              void* d_out, int out_size)
{
    const float* X    = (const float*)d_in[0];  // [B,N,HID]
    const void*  mask = d_in[1];                // [N,N]
    const float* Wqkv = (const float*)d_in[2];  // [1536,512]
    const float* bqkv = (const float*)d_in[3];  // [1536]
    const float* Wo   = (const float*)d_in[4];  // [512,512]
    const float* bo   = (const float*)d_in[5];  // [512]
    float* out = (float*)d_out;

    cudaFuncSetAttribute(attn_kernel,
                         cudaFuncAttributeMaxDynamicSharedMemorySize, ATTN_SMEM);
    cudaFuncSetAttribute(mma_tn,
                         cudaFuncAttributeMaxDynamicSharedMemorySize, GEMM_SMEM);

    float *qkv_p = nullptr, *ctx_p = nullptr, *xt_p = nullptr;
    float *wq_p = nullptr, *wo_p = nullptr;
    cudaGetSymbolAddress((void**)&qkv_p, g_qkv);
    cudaGetSymbolAddress((void**)&ctx_p, g_ctx);
    cudaGetSymbolAddress((void**)&xt_p, g_xt);
    cudaGetSymbolAddress((void**)&wq_p, g_wqkv);
    cudaGetSymbolAddress((void**)&wo_p, g_wo);

    float* attn_p = ((size_t)out_size >= OUT_OFF + ATTN_SIZE) ? out + OUT_OFF
                                                              : nullptr;

    normalize_mask_kernel<<<1, 32>>>(mask);

    // Pre-round inputs/weights to tf32 (rna) so the MMA path is unbiased.
    {
        int n4 = (int)(OUT_OFF / 4);                       // 16,777,216
        round_tf32_kernel<<<n4 / 256, 256>>>(X, xt_p, n4);
        int w4 = 3 * HID * HID / 4;                        // 196,608
        round_tf32_kernel<<<(w4 + 255) / 256, 256>>>(Wqkv, wq_p, w4);
        int o4 = HID * HID / 4;                            // 65,536
        round_tf32_kernel<<<(o4 + 255) / 256, 256>>>(Wo, wo_p, o4);
    }

    dim3 g1(3 * HID / BN, M_TOT / BM);   // (12, 1024)
    mma_tn<<<g1, 256, GEMM_SMEM>>>(xt_p, wq_p, bqkv, qkv_p, M_TOT, 3 * HID, HID);

    attn_kernel<<<B_, 256, ATTN_SMEM>>>(qkv_p, attn_p, ctx_p);

    dim3 g2(HID / BN, M_TOT / BM);       // (4, 1024)
    mma_tn<<<g2, 256, GEMM_SMEM>>>(ctx_p, wo_p, bo, out, M_TOT, HID, HID);
}

// round 3
// speedup vs baseline: 3.0720x; 1.0546x over previous
#include <cuda_runtime.h>
#include <math.h>
#include <stdint.h>

// Problem constants
#define B_    4096
#define N_    32
#define H_    8
#define HID   512
#define M_TOT (B_ * N_)                         // 131072
#define OUT_OFF ((size_t)M_TOT * HID)           // 67108864 floats
#define ATTN_SIZE ((size_t)B_ * H_ * N_ * N_)   // 33554432

// Scratch (device globals: allocation-guard safe)
__device__ float g_qkv[(size_t)M_TOT * 3 * HID];     // [B*N, 1536]
__device__ float g_ctx[(size_t)M_TOT * HID];         // [B*N, 512] (tf32-rounded)
__device__ unsigned g_mask_bits[32];

// ---------------------------------------------------------------------------
// Mask normalizer (dtype-agnostic: 1-byte bool vs 4-byte int/float)
// ---------------------------------------------------------------------------
__global__ void normalize_mask_kernel(const void* maskp) {
    int i = threadIdx.x;  // 0..31
    const unsigned char* m8 = (const unsigned char*)maskp;
    unsigned diag_ok = __ballot_sync(0xffffffffu, m8[i * 33] != 0);
    unsigned bits = 0;
    if (diag_ok == 0xffffffffu) {
        for (int j = 0; j < 32; j++)
            bits |= (unsigned)(m8[i * 32 + j] != 0) << j;
    } else {
        const int* m32 = (const int*)maskp;
        for (int j = 0; j < 32; j++)
            bits |= (unsigned)(m32[i * 32 + j] != 0) << j;
    }
    g_mask_bits[i] = bits;
}

__device__ __forceinline__ float to_tf32(float x) {
    uint32_t u;
    asm("cvt.rna.tf32.f32 %0, %1;" : "=r"(u) : "f"(x));
    return __uint_as_float(u);
}
__device__ __forceinline__ uint32_t to_tf32_u(uint32_t x) {
    uint32_t u;
    asm("cvt.rna.tf32.f32 %0, %1;" : "=r"(u) : "f"(__uint_as_float(x)));
    return u;
}

// ---------------------------------------------------------------------------
// TF32 tensor-core GEMM (TN): C[M,N] = A[M,K] @ W[N,K]^T + bias[N]
// fp32 inputs; tf32 rounding (rna) fused into the fragment loads.
// 128x128x32 tile, 256 threads, 8 warps x (64x32), m16n8k8, cp.async x2.
// Requires M%128==0, N%128==0, K%32==0, K/32 >= 2.
// ---------------------------------------------------------------------------
#define BM 128
#define BN 128
#define BK 32
#define PAD 36
#define TILE_F ((BM + BN) * PAD)            // 9216 floats per stage
#define GEMM_SMEM (2 * TILE_F * 4)          // 73728 bytes

__device__ __forceinline__ void cp16(uint32_t dst, const void* src) {
    asm volatile("cp.async.cg.shared.global [%0], [%1], 16;\n"
                 :: "r"(dst), "l"(src));
}

__global__ __launch_bounds__(256, 2) void mma_tn(
    const float* __restrict__ A, const float* __restrict__ W,
    const float* __restrict__ bias, float* __restrict__ C,
    int M, int N, int K)
{
    extern __shared__ float sh[];
    const int tid = threadIdx.x;
    const int bm = blockIdx.y * BM;
    const int bn = blockIdx.x * BN;

    const uint32_t sbase = (uint32_t)__cvta_generic_to_shared(sh);

    const int lrow = tid >> 3;          // 0..31
    const int lk = (tid & 7) * 4;       // 0..28
    const float* Ag = A + (size_t)(bm + lrow) * K + lk;
    const float* Wg = W + (size_t)(bn + lrow) * K + lk;

    auto issue = [&](int k0, int s) {
        uint32_t abuf = sbase + (uint32_t)(s * TILE_F) * 4u;
        uint32_t bbuf = abuf + BM * PAD * 4u;
        #pragma unroll
        for (int i = 0; i < 4; i++) {
            int m = lrow + i * 32;
            cp16(abuf + (uint32_t)(m * PAD + lk) * 4u, Ag + (size_t)(i * 32) * K + k0);
            cp16(bbuf + (uint32_t)(m * PAD + lk) * 4u, Wg + (size_t)(i * 32) * K + k0);
        }
        asm volatile("cp.async.commit_group;\n");
    };

    const int warp = tid >> 5, lane = tid & 31;
    const int wm = (warp >> 2) * 64;    // 0 or 64
    const int wn = (warp & 3) * 32;     // 0,32,64,96
    const int qr = lane >> 2;           // 0..7
    const int qc = lane & 3;            // 0..3

    float acc[4][4][4];
    #pragma unroll
    for (int a = 0; a < 4; a++)
        #pragma unroll
        for (int b = 0; b < 4; b++)
            #pragma unroll
            for (int c = 0; c < 4; c++) acc[a][b][c] = 0.f;

    const int nIter = K / BK;
    issue(0, 0);
    issue(BK, 1);

    for (int it = 0; it < nIter; it++) {
        if (it + 1 < nIter) asm volatile("cp.async.wait_group 1;\n");
        else                asm volatile("cp.async.wait_group 0;\n");
        __syncthreads();

        const uint32_t* Au = (const uint32_t*)(sh + (it & 1) * TILE_F);
        const uint32_t* Bu = Au + BM * PAD;

        #pragma unroll
        for (int ks = 0; ks < 4; ks++) {
            uint32_t af[4][4], bf[4][2];
            const int kk = ks * 8 + qc;
            #pragma unroll
            for (int mt = 0; mt < 4; mt++) {
                int base = (wm + mt * 16 + qr) * PAD + kk;
                af[mt][0] = to_tf32_u(Au[base]);
                af[mt][1] = to_tf32_u(Au[base + 8 * PAD]);
                af[mt][2] = to_tf32_u(Au[base + 4]);
                af[mt][3] = to_tf32_u(Au[base + 8 * PAD + 4]);
            }
            #pragma unroll
            for (int nt = 0; nt < 4; nt++) {
                int base = (wn + nt * 8 + qr) * PAD + kk;
                bf[nt][0] = to_tf32_u(Bu[base]);
                bf[nt][1] = to_tf32_u(Bu[base + 4]);
            }
            #pragma unroll
            for (int mt = 0; mt < 4; mt++)
                #pragma unroll
                for (int nt = 0; nt < 4; nt++)
                    asm volatile(
                        "mma.sync.aligned.m16n8k8.row.col.f32.tf32.tf32.f32 "
                        "{%0,%1,%2,%3}, {%4,%5,%6,%7}, {%8,%9}, {%0,%1,%2,%3};\n"
                        : "+f"(acc[mt][nt][0]), "+f"(acc[mt][nt][1]),
                          "+f"(acc[mt][nt][2]), "+f"(acc[mt][nt][3])
                        : "r"(af[mt][0]), "r"(af[mt][1]),
                          "r"(af[mt][2]), "r"(af[mt][3]),
                          "r"(bf[nt][0]), "r"(bf[nt][1]));
        }
        __syncthreads();
        if (it + 2 < nIter) issue((it + 2) * BK, it & 1);
    }

    #pragma unroll
    for (int nt = 0; nt < 4; nt++) {
        const int col = bn + wn + nt * 8 + qc * 2;
        const float2 bv = *(const float2*)(bias + col);
        #pragma unroll
        for (int mt = 0; mt < 4; mt++) {
            const int row = bm + wm + mt * 16 + qr;
            float2 v0 = { acc[mt][nt][0] + bv.x, acc[mt][nt][1] + bv.y };
            float2 v1 = { acc[mt][nt][2] + bv.x, acc[mt][nt][3] + bv.y };
            *(float2*)(C + (size_t)row * N + col) = v0;
            *(float2*)(C + (size_t)(row + 8) * N + col) = v1;
        }
    }
}

// ---------------------------------------------------------------------------
// Attention: one block per batch b, one warp per head h.
// Per-warp smem: one 32x65 tile (q -> k -> v, reused) + 32x33 prob buffer.
// 100,352 B/CTA -> 2 CTAs/SM. ctx out is tf32-rounded for GEMM2.
// ---------------------------------------------------------------------------
#define WTILE 2080                        // 32*65
#define WPROB 1056                        // 32*33
#define WARP_F (WTILE + WPROB)            // 3136 floats
#define ATTN_SMEM (8 * WARP_F * 4)        // 100352 bytes

__global__ __launch_bounds__(256, 2) void attn_kernel(
    const float* __restrict__ qkv,
    float* __restrict__ attn_out,
    float* __restrict__ ctx_out)
{
    extern __shared__ float sh[];
    const int b = blockIdx.x;
    const int warp = threadIdx.x >> 5;    // head
    const int lane = threadIdx.x & 31;

    float* buf  = sh + warp * WARP_F;     // 32x65 q/k/v tile
    float* pbuf = buf + WTILE;            // 32x33 scores/probs

    const float* base = qkv + (size_t)b * 32 * 1536 + warp * 64;
    const int i = lane;

    // ---- load q tile
    #pragma unroll 4
    for (int r = 0; r < 32; r++) {
        const float* row = base + (size_t)r * 1536;
        buf[r * 65 + lane]      = row[lane];
        buf[r * 65 + lane + 32] = row[lane + 32];
    }
    __syncwarp();

    float qa[64];
    #pragma unroll
    for (int d = 0; d < 64; d++) qa[d] = buf[i * 65 + d];
    __syncwarp();

    // ---- overwrite with k tile
    #pragma unroll 4
    for (int r = 0; r < 32; r++) {
        const float* row = base + (size_t)r * 1536 + 512;
        buf[r * 65 + lane]      = row[lane];
        buf[r * 65 + lane + 32] = row[lane + 32];
    }
    __syncwarp();

    // ---- scores -> pbuf, track row max
    const unsigned bits = g_mask_bits[i];
    float mx = -1e30f;
    #pragma unroll 4
    for (int j = 0; j < 32; j++) {
        float acc = 0.f;
        #pragma unroll
        for (int d = 0; d < 64; d++) acc += qa[d] * buf[j * 65 + d];
        float s = ((bits >> j) & 1u) ? acc * 0.125f : -1e9f;
        mx = fmaxf(mx, s);
        pbuf[i * 33 + j] = s;
    }

    // ---- softmax over pbuf row i
    float sum = 0.f;
    #pragma unroll
    for (int j = 0; j < 32; j++) {
        float e = __expf(pbuf[i * 33 + j] - mx);
        pbuf[i * 33 + j] = e;
        sum += e;
    }
    const float inv = 1.f / sum;
    #pragma unroll
    for (int j = 0; j < 32; j++) pbuf[i * 33 + j] *= inv;
    __syncwarp();

    // ---- attn output (coalesced)
    if (attn_out) {
        float* ao = attn_out + ((size_t)(b * 8 + warp) * 32) * 32;
        #pragma unroll 4
        for (int r = 0; r < 32; r++) ao[r * 32 + lane] = pbuf[r * 33 + lane];
    }

    // ---- overwrite with v tile
    #pragma unroll 4
    for (int r = 0; r < 32; r++) {
        const float* row = base + (size_t)r * 1536 + 1024;
        buf[r * 65 + lane]      = row[lane];
        buf[r * 65 + lane + 32] = row[lane + 32];
    }
    __syncwarp();

    // ---- ctx[r, d] = sum_j p[r,j] * v[j,d]
    #pragma unroll 2
    for (int r = 0; r < 32; r++) {
        float c0 = 0.f, c1 = 0.f;
        #pragma unroll
        for (int j = 0; j < 32; j++) {
            float p = pbuf[r * 33 + j];
            c0 += p * buf[j * 65 + lane];
            c1 += p * buf[j * 65 + lane + 32];
        }
        float* co = ctx_out + (size_t)(b * 32 + r) * HID + warp * 64;
        co[lane]      = to_tf32(c0);
        co[lane + 32] = to_tf32(c1);
    }
}

// ---------------------------------------------------------------------------
extern "C" void kernel_launch(void* const* d_in, const int* in_sizes, int n_in,
                              void* d_out, int out_size)
{
    const float* X    = (const float*)d_in[0];  // [B,N,HID]
    const void*  mask = d_in[1];                // [N,N]
    const float* Wqkv = (const float*)d_in[2];  // [1536,512]
    const float* bqkv = (const float*)d_in[3];  // [1536]
    const float* Wo   = (const float*)d_in[4];  // [512,512]
    const float* bo   = (const float*)d_in[5];  // [512]
    float* out = (float*)d_out;

    cudaFuncSetAttribute(attn_kernel,
                         cudaFuncAttributeMaxDynamicSharedMemorySize, ATTN_SMEM);
    cudaFuncSetAttribute(mma_tn,
                         cudaFuncAttributeMaxDynamicSharedMemorySize, GEMM_SMEM);

    float *qkv_p = nullptr, *ctx_p = nullptr;
    cudaGetSymbolAddress((void**)&qkv_p, g_qkv);
    cudaGetSymbolAddress((void**)&ctx_p, g_ctx);

    float* attn_p = ((size_t)out_size >= OUT_OFF + ATTN_SIZE) ? out + OUT_OFF
                                                              : nullptr;

    normalize_mask_kernel<<<1, 32>>>(mask);

    dim3 g1(3 * HID / BN, M_TOT / BM);   // (12, 1024)
    mma_tn<<<g1, 256, GEMM_SMEM>>>(X, Wqkv, bqkv, qkv_p, M_TOT, 3 * HID, HID);

    attn_kernel<<<B_, 256, ATTN_SMEM>>>(qkv_p, attn_p, ctx_p);

    dim3 g2(HID / BN, M_TOT / BM);       // (4, 1024)
    mma_tn<<<g2, 256, GEMM_SMEM>>>(ctx_p, Wo, bo, out, M_TOT, HID, HID);
}

// round 5
// speedup vs baseline: 3.9904x; 1.2990x over previous
#include <cuda_runtime.h>
#include <cuda_fp16.h>
#include <math.h>
#include <stdint.h>

// Problem constants
#define B_    4096
#define N_    32
#define H_    8
#define HID   512
#define M_TOT (B_ * N_)                         // 131072
#define OUT_OFF ((size_t)M_TOT * HID)           // 67108864 floats
#define ATTN_SIZE ((size_t)B_ * H_ * N_ * N_)   // 33554432

// Scratch (device globals: allocation-guard safe)
__device__ float  g_qkv[(size_t)M_TOT * 3 * HID];   // [B*N, 1536] fp32 (attn input)
__device__ __half g_ctxh[(size_t)M_TOT * HID];      // [B*N, 512] fp16 (GEMM2 A)
__device__ __half g_xh[(size_t)M_TOT * HID];        // fp16 X
__device__ __half g_wqh[(size_t)3 * HID * HID];     // fp16 Wqkv
__device__ __half g_woh[(size_t)HID * HID];         // fp16 Wo
__device__ unsigned g_mask_bits[32];

// ---------------------------------------------------------------------------
// Mask normalizer (dtype-agnostic: 1-byte bool vs 4-byte int/float)
// ---------------------------------------------------------------------------
__global__ void normalize_mask_kernel(const void* maskp) {
    int i = threadIdx.x;  // 0..31
    const unsigned char* m8 = (const unsigned char*)maskp;
    unsigned diag_ok = __ballot_sync(0xffffffffu, m8[i * 33] != 0);
    unsigned bits = 0;
    if (diag_ok == 0xffffffffu) {
        for (int j = 0; j < 32; j++)
            bits |= (unsigned)(m8[i * 32 + j] != 0) << j;
    } else {
        const int* m32 = (const int*)maskp;
        for (int j = 0; j < 32; j++)
            bits |= (unsigned)(m32[i * 32 + j] != 0) << j;
    }
    g_mask_bits[i] = bits;
}

// ---------------------------------------------------------------------------
// fp32 -> fp16 conversion, 8 floats per thread (32B read / 16B write)
// ---------------------------------------------------------------------------
__global__ void cvt_f32_f16_kernel(const float* __restrict__ in,
                                   __half* __restrict__ out, int n8) {
    int i = blockIdx.x * blockDim.x + threadIdx.x;
    if (i >= n8) return;
    float4 a = ((const float4*)in)[2 * i];
    float4 b = ((const float4*)in)[2 * i + 1];
    __half2 h[4];
    h[0] = __floats2half2_rn(a.x, a.y);
    h[1] = __floats2half2_rn(a.z, a.w);
    h[2] = __floats2half2_rn(b.x, b.y);
    h[3] = __floats2half2_rn(b.z, b.w);
    ((uint4*)out)[i] = *(uint4*)h;
}

// ---------------------------------------------------------------------------
// FP16 tensor-core GEMM (TN): C[M,N] = A[M,K] @ W[N,K]^T + bias[N]
// A, W fp16; C fp32. 128x128x32 tile, 256 threads, 8 warps x (64x32),
// m16n8k16 mma + ldmatrix.x4, cp.async double buffering.
// smem rows padded to 40 halves (80B): conflict-free LDSM, 16B-aligned.
// Requires M%128==0, N%128==0, K%32==0, K/32 >= 2.
// ---------------------------------------------------------------------------
#define BM 128
#define BN 128
#define BK 32
#define SROW 40                              // fp16 units per smem row
#define TILE_H (BM * SROW)                   // 5120 fp16 per A tile
#define STAGE_H (2 * TILE_H)                 // A + B per stage
#define GEMM_SMEM (2 * STAGE_H * 2)          // 40960 bytes

__device__ __forceinline__ void cp16(uint32_t dst, const void* src) {
    asm volatile("cp.async.cg.shared.global [%0], [%1], 16;\n"
                 :: "r"(dst), "l"(src));
}
__device__ __forceinline__ void ldsm_x4(uint32_t (&r)[4], uint32_t addr) {
    asm volatile("ldmatrix.sync.aligned.m8n8.x4.shared.b16 {%0,%1,%2,%3}, [%4];\n"
                 : "=r"(r[0]), "=r"(r[1]), "=r"(r[2]), "=r"(r[3]) : "r"(addr));
}

__global__ __launch_bounds__(256, 2) void hmma_tn(
    const __half* __restrict__ A, const __half* __restrict__ W,
    const float* __restrict__ bias, float* __restrict__ C,
    int M, int N, int K)
{
    extern __shared__ __half sh[];
    const int tid = threadIdx.x;
    const int bm = blockIdx.y * BM;
    const int bn = blockIdx.x * BN;

    const uint32_t sbase = (uint32_t)__cvta_generic_to_shared(sh);

    // Loader: thread t copies 2x16B of A and 2x16B of B per stage.
    const int lrow = tid >> 1;                 // 0..127
    const int lk0 = (tid & 1) * 16;            // 0 or 16 (halves)
    const __half* Ag = A + (size_t)(bm + lrow) * K + lk0;
    const __half* Wg = W + (size_t)(bn + lrow) * K + lk0;

    auto issue = [&](int k0, int s) {
        uint32_t abuf = sbase + (uint32_t)(s * STAGE_H) * 2u;
        uint32_t bbuf = abuf + TILE_H * 2u;
        #pragma unroll
        for (int o = 0; o < 2; o++) {
            uint32_t soff = (uint32_t)(lrow * SROW + lk0 + o * 8) * 2u;
            cp16(abuf + soff, Ag + k0 + o * 8);
            cp16(bbuf + soff, Wg + k0 + o * 8);
        }
        asm volatile("cp.async.commit_group;\n");
    };

    const int warp = tid >> 5, lane = tid & 31;
    const int wm = (warp >> 2) * 64;    // 0 or 64
    const int wn = (warp & 3) * 32;     // 0,32,64,96
    const int qr = lane >> 2;           // 0..7
    const int qc = lane & 3;            // 0..3
    const int l15 = lane & 15;
    const int lhalf = lane >> 4;

    float acc[4][4][4];
    #pragma unroll
    for (int a = 0; a < 4; a++)
        #pragma unroll
        for (int b = 0; b < 4; b++)
            #pragma unroll
            for (int c = 0; c < 4; c++) acc[a][b][c] = 0.f;

    const int nIter = K / BK;
    issue(0, 0);
    issue(BK, 1);

    for (int it = 0; it < nIter; it++) {
        if (it + 1 < nIter) asm volatile("cp.async.wait_group 1;\n");
        else                asm volatile("cp.async.wait_group 0;\n");
        __syncthreads();

        const uint32_t abase = sbase + (uint32_t)((it & 1) * STAGE_H) * 2u;
        const uint32_t bbase = abase + TILE_H * 2u;

        #pragma unroll
        for (int ks = 0; ks < 2; ks++) {
            const int kcol = ks * 16 + lhalf * 8;
            // A fragments: 4 m-tiles of 16, ldmatrix x4 each
            uint32_t af[4][4];
            #pragma unroll
            for (int mt = 0; mt < 4; mt++)
                ldsm_x4(af[mt], abase +
                        (uint32_t)((wm + mt * 16 + l15) * SROW + kcol) * 2u);
            // B fragments: 2 n16-groups, ldmatrix x4 each
            uint32_t bf[2][4];
            #pragma unroll
            for (int ng = 0; ng < 2; ng++)
                ldsm_x4(bf[ng], bbase +
                        (uint32_t)((wn + ng * 16 + l15) * SROW + kcol) * 2u);

            #pragma unroll
            for (int mt = 0; mt < 4; mt++)
                #pragma unroll
                for (int nt = 0; nt < 4; nt++) {
                    // n-tile nt: group ng = nt>>1, frags {r0,r2} or {r1,r3}
                    const uint32_t b0 = bf[nt >> 1][(nt & 1)];
                    const uint32_t b1 = bf[nt >> 1][(nt & 1) + 2];
                    asm volatile(
                        "mma.sync.aligned.m16n8k16.row.col.f32.f16.f16.f32 "
                        "{%0,%1,%2,%3}, {%4,%5,%6,%7}, {%8,%9}, {%0,%1,%2,%3};\n"
                        : "+f"(acc[mt][nt][0]), "+f"(acc[mt][nt][1]),
                          "+f"(acc[mt][nt][2]), "+f"(acc[mt][nt][3])
                        : "r"(af[mt][0]), "r"(af[mt][1]),
                          "r"(af[mt][2]), "r"(af[mt][3]),
                          "r"(b0), "r"(b1));
                }
        }
        __syncthreads();
        if (it + 2 < nIter) issue((it + 2) * BK, it & 1);
    }

    // Epilogue: bias add + float2 stores
    #pragma unroll
    for (int nt = 0; nt < 4; nt++) {
        const int col = bn + wn + nt * 8 + qc * 2;
        const float2 bv = *(const float2*)(bias + col);
        #pragma unroll
        for (int mt = 0; mt < 4; mt++) {
            const int row = bm + wm + mt * 16 + qr;
            float2 v0 = { acc[mt][nt][0] + bv.x, acc[mt][nt][1] + bv.y };
            float2 v1 = { acc[mt][nt][2] + bv.x, acc[mt][nt][3] + bv.y };
            *(float2*)(C + (size_t)row * N + col) = v0;
            *(float2*)(C + (size_t)(row + 8) * N + col) = v1;
        }
    }
}

// ---------------------------------------------------------------------------
// Attention: one block per batch b, one warp per head h. fp32 math.
// Per-warp smem: one 32x65 tile (q -> k -> v, reused) + 32x33 prob buffer.
// ctx written as fp16 (feeds GEMM2).
// ---------------------------------------------------------------------------
#define WTILE 2080                        // 32*65
#define WPROB 1056                        // 32*33
#define WARP_F (WTILE + WPROB)            // 3136 floats
#define ATTN_SMEM (8 * WARP_F * 4)        // 100352 bytes

__global__ __launch_bounds__(256, 2) void attn_kernel(
    const float* __restrict__ qkv,
    float* __restrict__ attn_out,
    __half* __restrict__ ctx_out)
{
    extern __shared__ float shf[];
    const int b = blockIdx.x;
    const int warp = threadIdx.x >> 5;    // head
    const int lane = threadIdx.x & 31;

    float* buf  = shf + warp * WARP_F;    // 32x65 q/k/v tile
    float* pbuf = buf + WTILE;            // 32x33 scores/probs

    const float* base = qkv + (size_t)b * 32 * 1536 + warp * 64;
    const int i = lane;

    // ---- load q tile
    #pragma unroll 4
    for (int r = 0; r < 32; r++) {
        const float* row = base + (size_t)r * 1536;
        buf[r * 65 + lane]      = row[lane];
        buf[r * 65 + lane + 32] = row[lane + 32];
    }
    __syncwarp();

    float qa[64];
    #pragma unroll
    for (int d = 0; d < 64; d++) qa[d] = buf[i * 65 + d];
    __syncwarp();

    // ---- overwrite with k tile
    #pragma unroll 4
    for (int r = 0; r < 32; r++) {
        const float* row = base + (size_t)r * 1536 + 512;
        buf[r * 65 + lane]      = row[lane];
        buf[r * 65 + lane + 32] = row[lane + 32];
    }
    __syncwarp();

    // ---- scores -> pbuf, track row max
    const unsigned bits = g_mask_bits[i];
    float mx = -1e30f;
    #pragma unroll 4
    for (int j = 0; j < 32; j++) {
        float acc = 0.f;
        #pragma unroll
        for (int d = 0; d < 64; d++) acc += qa[d] * buf[j * 65 + d];
        float s = ((bits >> j) & 1u) ? acc * 0.125f : -1e9f;
        mx = fmaxf(mx, s);
        pbuf[i * 33 + j] = s;
    }

    // ---- softmax over pbuf row i
    float sum = 0.f;
    #pragma unroll
    for (int j = 0; j < 32; j++) {
        float e = __expf(pbuf[i * 33 + j] - mx);
        pbuf[i * 33 + j] = e;
        sum += e;
    }
    const float inv = 1.f / sum;
    #pragma unroll
    for (int j = 0; j < 32; j++) pbuf[i * 33 + j] *= inv;
    __syncwarp();

    // ---- attn output (coalesced)
    if (attn_out) {
        float* ao = attn_out + ((size_t)(b * 8 + warp) * 32) * 32;
        #pragma unroll 4
        for (int r = 0; r < 32; r++) ao[r * 32 + lane] = pbuf[r * 33 + lane];
    }

    // ---- overwrite with v tile
    #pragma unroll 4
    for (int r = 0; r < 32; r++) {
        const float* row = base + (size_t)r * 1536 + 1024;
        buf[r * 65 + lane]      = row[lane];
        buf[r * 65 + lane + 32] = row[lane + 32];
    }
    __syncwarp();

    // ---- ctx[r, d] = sum_j p[r,j] * v[j,d] -> fp16
    #pragma unroll 2
    for (int r = 0; r < 32; r++) {
        float c0 = 0.f, c1 = 0.f;
        #pragma unroll
        for (int j = 0; j < 32; j++) {
            float p = pbuf[r * 33 + j];
            c0 += p * buf[j * 65 + lane];
            c1 += p * buf[j * 65 + lane + 32];
        }
        __half* co = ctx_out + (size_t)(b * 32 + r) * HID + warp * 64;
        co[lane]      = __float2half_rn(c0);
        co[lane + 32] = __float2half_rn(c1);
    }
}

// ---------------------------------------------------------------------------
extern "C" void kernel_launch(void* const* d_in, const int* in_sizes, int n_in,
                              void* d_out, int out_size)
{
    const float* X    = (const float*)d_in[0];  // [B,N,HID]
    const void*  mask = d_in[1];                // [N,N]
    const float* Wqkv = (const float*)d_in[2];  // [1536,512]
    const float* bqkv = (const float*)d_in[3];  // [1536]
    const float* Wo   = (const float*)d_in[4];  // [512,512]
    const float* bo   = (const float*)d_in[5];  // [512]
    float* out = (float*)d_out;

    cudaFuncSetAttribute(attn_kernel,
                         cudaFuncAttributeMaxDynamicSharedMemorySize, ATTN_SMEM);
    cudaFuncSetAttribute(hmma_tn,
                         cudaFuncAttributeMaxDynamicSharedMemorySize, GEMM_SMEM);

    float* qkv_p = nullptr;
    __half *ctx_p = nullptr, *xh_p = nullptr, *wq_p = nullptr, *wo_p = nullptr;
    cudaGetSymbolAddress((void**)&qkv_p, g_qkv);
    cudaGetSymbolAddress((void**)&ctx_p, g_ctxh);
    cudaGetSymbolAddress((void**)&xh_p, g_xh);
    cudaGetSymbolAddress((void**)&wq_p, g_wqh);
    cudaGetSymbolAddress((void**)&wo_p, g_woh);

    float* attn_p = ((size_t)out_size >= OUT_OFF + ATTN_SIZE) ? out + OUT_OFF
                                                              : nullptr;

    normalize_mask_kernel<<<1, 32>>>(mask);

    // Convert inputs/weights to fp16
    {
        int n8 = (int)(OUT_OFF / 8);                       // 8,388,608
        cvt_f32_f16_kernel<<<n8 / 256, 256>>>(X, xh_p, n8);
        int w8 = 3 * HID * HID / 8;
        cvt_f32_f16_kernel<<<(w8 + 255) / 256, 256>>>(Wqkv, wq_p, w8);
        int o8 = HID * HID / 8;
        cvt_f32_f16_kernel<<<(o8 + 255) / 256, 256>>>(Wo, wo_p, o8);
    }

    dim3 g1(3 * HID / BN, M_TOT / BM);   // (12, 1024)
    hmma_tn<<<g1, 256, GEMM_SMEM>>>(xh_p, wq_p, bqkv, qkv_p, M_TOT, 3 * HID, HID);

    attn_kernel<<<B_, 256, ATTN_SMEM>>>(qkv_p, attn_p, ctx_p);

    dim3 g2(HID / BN, M_TOT / BM);       // (4, 1024)
    hmma_tn<<<g2, 256, GEMM_SMEM>>>(ctx_p, wo_p, bo, out, M_TOT, HID, HID);
}

// round 7
// speedup vs baseline: 4.0829x; 1.0232x over previous
#include <cuda_runtime.h>
#include <cuda_fp16.h>
#include <math.h>
#include <stdint.h>

// Problem constants
#define B_    4096
#define N_    32
#define H_    8
#define HID   512
#define M_TOT (B_ * N_)                         // 131072
#define OUT_OFF ((size_t)M_TOT * HID)           // 67108864 floats
#define ATTN_SIZE ((size_t)B_ * H_ * N_ * N_)   // 33554432

// Scratch (device globals: allocation-guard safe)
__device__ __half g_qkvh[(size_t)M_TOT * 3 * HID];  // [B*N, 1536] fp16
__device__ __half g_ctxh[(size_t)M_TOT * HID];      // [B*N, 512] fp16
__device__ __half g_xh[(size_t)M_TOT * HID];        // fp16 X
__device__ __half g_wqh[(size_t)3 * HID * HID];     // fp16 Wqkv
__device__ __half g_woh[(size_t)HID * HID];         // fp16 Wo
__device__ unsigned g_mask_bits[32];

// ---------------------------------------------------------------------------
// Mask normalizer (dtype-agnostic: 1-byte bool vs 4-byte int/float)
// ---------------------------------------------------------------------------
__global__ void normalize_mask_kernel(const void* maskp) {
    int i = threadIdx.x;  // 0..31
    const unsigned char* m8 = (const unsigned char*)maskp;
    unsigned diag_ok = __ballot_sync(0xffffffffu, m8[i * 33] != 0);
    unsigned bits = 0;
    if (diag_ok == 0xffffffffu) {
        for (int j = 0; j < 32; j++)
            bits |= (unsigned)(m8[i * 32 + j] != 0) << j;
    } else {
        const int* m32 = (const int*)maskp;
        for (int j = 0; j < 32; j++)
            bits |= (unsigned)(m32[i * 32 + j] != 0) << j;
    }
    g_mask_bits[i] = bits;
}

// ---------------------------------------------------------------------------
// fp32 -> fp16 conversion, 8 floats per thread
// ---------------------------------------------------------------------------
__global__ void cvt_f32_f16_kernel(const float* __restrict__ in,
                                   __half* __restrict__ out, int n8) {
    int i = blockIdx.x * blockDim.x + threadIdx.x;
    if (i >= n8) return;
    float4 a = ((const float4*)in)[2 * i];
    float4 b = ((const float4*)in)[2 * i + 1];
    __half2 h[4];
    h[0] = __floats2half2_rn(a.x, a.y);
    h[1] = __floats2half2_rn(a.z, a.w);
    h[2] = __floats2half2_rn(b.x, b.y);
    h[3] = __floats2half2_rn(b.z, b.w);
    ((uint4*)out)[i] = *(uint4*)h;
}

// ---------------------------------------------------------------------------
// FP16 tensor-core GEMM (TN): C[M,N] = A[M,K] @ W[N,K]^T + bias[N]
// 128x128x32 tile, 256 threads, 8 warps x (64x32), m16n8k16 + ldmatrix.x4.
// 3-stage cp.async pipeline, ONE __syncthreads per K-iter.
// smem rows padded to 40 halves (80B): conflict-free LDSM, 16B-aligned.
// HOUT: write C as fp16 (half2) instead of fp32.
// ---------------------------------------------------------------------------
#define BM 128
#define BN 128
#define BK 32
#define SROW 40                              // fp16 units per smem row
#define TILE_H (BM * SROW)                   // 5120 fp16 per A tile
#define STAGE_H (2 * TILE_H)                 // A + B per stage
#define NSTAGE 3
#define GEMM_SMEM (NSTAGE * STAGE_H * 2)     // 61440 bytes

__device__ __forceinline__ void cp16(uint32_t dst, const void* src) {
    asm volatile("cp.async.cg.shared.global [%0], [%1], 16;\n"
                 :: "r"(dst), "l"(src));
}
__device__ __forceinline__ void ldsm_x4(uint32_t (&r)[4], uint32_t addr) {
    asm volatile("ldmatrix.sync.aligned.m8n8.x4.shared.b16 {%0,%1,%2,%3}, [%4];\n"
                 : "=r"(r[0]), "=r"(r[1]), "=r"(r[2]), "=r"(r[3]) : "r"(addr));
}

template <bool HOUT>
__global__ __launch_bounds__(256, 2) void hmma_tn(
    const __half* __restrict__ A, const __half* __restrict__ W,
    const float* __restrict__ bias, void* __restrict__ Cv,
    int M, int N, int K)
{
    extern __shared__ __half sh[];
    const int tid = threadIdx.x;
    const int bm = blockIdx.y * BM;
    const int bn = blockIdx.x * BN;

    const uint32_t sbase = (uint32_t)__cvta_generic_to_shared(sh);

    // Loader: thread t copies 2x16B of A and 2x16B of B per stage.
    const int lrow = tid >> 1;                 // 0..127
    const int lk0 = (tid & 1) * 16;            // 0 or 16 (halves)
    const __half* Ag = A + (size_t)(bm + lrow) * K + lk0;
    const __half* Wg = W + (size_t)(bn + lrow) * K + lk0;

    auto issue = [&](int k0, int s) {
        uint32_t abuf = sbase + (uint32_t)(s * STAGE_H) * 2u;
        uint32_t bbuf = abuf + TILE_H * 2u;
        #pragma unroll
        for (int o = 0; o < 2; o++) {
            uint32_t soff = (uint32_t)(lrow * SROW + lk0 + o * 8) * 2u;
            cp16(abuf + soff, Ag + k0 + o * 8);
            cp16(bbuf + soff, Wg + k0 + o * 8);
        }
        asm volatile("cp.async.commit_group;\n");
    };

    const int warp = tid >> 5, lane = tid & 31;
    const int wm = (warp >> 2) * 64;    // 0 or 64
    const int wn = (warp & 3) * 32;     // 0,32,64,96
    const int qr = lane >> 2;           // 0..7
    const int qc = lane & 3;            // 0..3
    const int l15 = lane & 15;
    const int lhalf = lane >> 4;

    float acc[4][4][4];
    #pragma unroll
    for (int a = 0; a < 4; a++)
        #pragma unroll
        for (int b = 0; b < 4; b++)
            #pragma unroll
            for (int c = 0; c < 4; c++) acc[a][b][c] = 0.f;

    const int nIter = K / BK;
    issue(0, 0);
    issue(BK, 1);

    for (int it = 0; it < nIter; it++) {
        if (it + 1 < nIter) asm volatile("cp.async.wait_group 1;\n");
        else                asm volatile("cp.async.wait_group 0;\n");
        __syncthreads();
        // Stage (it+2)%3 == (it-1)%3 was consumed at iter it-1; every thread
        // has passed that iteration's compute (they're past this barrier).
        if (it + 2 < nIter) issue((it + 2) * BK, (it + 2) % NSTAGE);

        const uint32_t abase = sbase + (uint32_t)((it % NSTAGE) * STAGE_H) * 2u;
        const uint32_t bbase = abase + TILE_H * 2u;

        #pragma unroll
        for (int ks = 0; ks < 2; ks++) {
            const int kcol = ks * 16 + lhalf * 8;
            uint32_t af[4][4];
            #pragma unroll
            for (int mt = 0; mt < 4; mt++)
                ldsm_x4(af[mt], abase +
                        (uint32_t)((wm + mt * 16 + l15) * SROW + kcol) * 2u);
            uint32_t bf[2][4];
            #pragma unroll
            for (int ng = 0; ng < 2; ng++)
                ldsm_x4(bf[ng], bbase +
                        (uint32_t)((wn + ng * 16 + l15) * SROW + kcol) * 2u);

            #pragma unroll
            for (int mt = 0; mt < 4; mt++)
                #pragma unroll
                for (int nt = 0; nt < 4; nt++) {
                    const uint32_t b0 = bf[nt >> 1][(nt & 1)];
                    const uint32_t b1 = bf[nt >> 1][(nt & 1) + 2];
                    asm volatile(
                        "mma.sync.aligned.m16n8k16.row.col.f32.f16.f16.f32 "
                        "{%0,%1,%2,%3}, {%4,%5,%6,%7}, {%8,%9}, {%0,%1,%2,%3};\n"
                        : "+f"(acc[mt][nt][0]), "+f"(acc[mt][nt][1]),
                          "+f"(acc[mt][nt][2]), "+f"(acc[mt][nt][3])
                        : "r"(af[mt][0]), "r"(af[mt][1]),
                          "r"(af[mt][2]), "r"(af[mt][3]),
                          "r"(b0), "r"(b1));
                }
        }
    }

    // Epilogue: bias add + stores
    #pragma unroll
    for (int nt = 0; nt < 4; nt++) {
        const int col = bn + wn + nt * 8 + qc * 2;
        const float2 bv = *(const float2*)(bias + col);
        #pragma unroll
        for (int mt = 0; mt < 4; mt++) {
            const int row = bm + wm + mt * 16 + qr;
            float2 v0 = { acc[mt][nt][0] + bv.x, acc[mt][nt][1] + bv.y };
            float2 v1 = { acc[mt][nt][2] + bv.x, acc[mt][nt][3] + bv.y };
            if (HOUT) {
                __half* C = (__half*)Cv;
                *(__half2*)(C + (size_t)row * N + col) =
                    __floats2half2_rn(v0.x, v0.y);
                *(__half2*)(C + (size_t)(row + 8) * N + col) =
                    __floats2half2_rn(v1.x, v1.y);
            } else {
                float* C = (float*)Cv;
                *(float2*)(C + (size_t)row * N + col) = v0;
                *(float2*)(C + (size_t)(row + 8) * N + col) = v1;
            }
        }
    }
}

// ---------------------------------------------------------------------------
// Attention: one block per batch b, one warp per head h. fp32 math on
// fp16 qkv. Per-warp smem: one 32x66 fp32 tile (q -> k -> v) + 32x33 probs.
// ---------------------------------------------------------------------------
#define TS 66                             // tile row stride (floats)
#define WTILE (32 * TS)                   // 2112
#define WPROB 1056                        // 32*33
#define WARP_F (WTILE + WPROB)            // 3168 floats
#define ATTN_SMEM (8 * WARP_F * 4)        // 101376 bytes

__global__ __launch_bounds__(256, 2) void attn_kernel(
    const __half* __restrict__ qkv,
    float* __restrict__ attn_out,
    __half* __restrict__ ctx_out)
{
    extern __shared__ float shf[];
    const int b = blockIdx.x;
    const int warp = threadIdx.x >> 5;    // head
    const int lane = threadIdx.x & 31;

    float* buf  = shf + warp * WARP_F;    // 32x66 q/k/v tile
    float* pbuf = buf + WTILE;            // 32x33 scores/probs

    const __half* base = qkv + (size_t)b * 32 * 1536 + warp * 64;
    const int i = lane;

    // ---- load q tile (half2 -> float2, conflict-free)
    #pragma unroll 4
    for (int r = 0; r < 32; r++) {
        const __half2 h = ((const __half2*)(base + (size_t)r * 1536))[lane];
        *(float2*)&buf[r * TS + 2 * lane] = __half22float2(h);
    }
    __syncwarp();

    float qa[64];
    #pragma unroll
    for (int d = 0; d < 64; d++) qa[d] = buf[i * TS + d];
    __syncwarp();

    // ---- overwrite with k tile
    #pragma unroll 4
    for (int r = 0; r < 32; r++) {
        const __half2 h = ((const __half2*)(base + (size_t)r * 1536 + 512))[lane];
        *(float2*)&buf[r * TS + 2 * lane] = __half22float2(h);
    }
    __syncwarp();

    // ---- scores -> pbuf, track row max
    const unsigned bits = g_mask_bits[i];
    float mx = -1e30f;
    #pragma unroll 4
    for (int j = 0; j < 32; j++) {
        float acc = 0.f;
        #pragma unroll
        for (int d = 0; d < 64; d++) acc += qa[d] * buf[j * TS + d];
        float s = ((bits >> j) & 1u) ? acc * 0.125f : -1e9f;
        mx = fmaxf(mx, s);
        pbuf[i * 33 + j] = s;
    }

    // ---- softmax over pbuf row i
    float sum = 0.f;
    #pragma unroll
    for (int j = 0; j < 32; j++) {
        float e = __expf(pbuf[i * 33 + j] - mx);
        pbuf[i * 33 + j] = e;
        sum += e;
    }
    const float inv = 1.f / sum;
    #pragma unroll
    for (int j = 0; j < 32; j++) pbuf[i * 33 + j] *= inv;
    __syncwarp();

    // ---- attn output (coalesced)
    if (attn_out) {
        float* ao = attn_out + ((size_t)(b * 8 + warp) * 32) * 32;
        #pragma unroll 4
        for (int r = 0; r < 32; r++) ao[r * 32 + lane] = pbuf[r * 33 + lane];
    }

    // ---- overwrite with v tile
    #pragma unroll 4
    for (int r = 0; r < 32; r++) {
        const __half2 h = ((const __half2*)(base + (size_t)r * 1536 + 1024))[lane];
        *(float2*)&buf[r * TS + 2 * lane] = __half22float2(h);
    }
    __syncwarp();

    // ---- ctx[r, d] = sum_j p[r,j] * v[j,d] -> fp16
    #pragma unroll 2
    for (int r = 0; r < 32; r++) {
        float c0 = 0.f, c1 = 0.f;
        #pragma unroll
        for (int j = 0; j < 32; j++) {
            float p = pbuf[r * 33 + j];
            c0 += p * buf[j * TS + lane];
            c1 += p * buf[j * TS + lane + 32];
        }
        __half* co = ctx_out + (size_t)(b * 32 + r) * HID + warp * 64;
        co[lane]      = __float2half_rn(c0);
        co[lane + 32] = __float2half_rn(c1);
    }
}

// ---------------------------------------------------------------------------
extern "C" void kernel_launch(void* const* d_in, const int* in_sizes, int n_in,
                              void* d_out, int out_size)
{
    const float* X    = (const float*)d_in[0];  // [B,N,HID]
    const void*  mask = d_in[1];                // [N,N]
    const float* Wqkv = (const float*)d_in[2];  // [1536,512]
    const float* bqkv = (const float*)d_in[3];  // [1536]
    const float* Wo   = (const float*)d_in[4];  // [512,512]
    const float* bo   = (const float*)d_in[5];  // [512]
    float* out = (float*)d_out;

    cudaFuncSetAttribute(attn_kernel,
                         cudaFuncAttributeMaxDynamicSharedMemorySize, ATTN_SMEM);
    cudaFuncSetAttribute(hmma_tn<true>,
                         cudaFuncAttributeMaxDynamicSharedMemorySize, GEMM_SMEM);
    cudaFuncSetAttribute(hmma_tn<false>,
                         cudaFuncAttributeMaxDynamicSharedMemorySize, GEMM_SMEM);

    __half *qkv_p = nullptr, *ctx_p = nullptr, *xh_p = nullptr;
    __half *wq_p = nullptr, *wo_p = nullptr;
    cudaGetSymbolAddress((void**)&qkv_p, g_qkvh);
    cudaGetSymbolAddress((void**)&ctx_p, g_ctxh);
    cudaGetSymbolAddress((void**)&xh_p, g_xh);
    cudaGetSymbolAddress((void**)&wq_p, g_wqh);
    cudaGetSymbolAddress((void**)&wo_p, g_woh);

    float* attn_p = ((size_t)out_size >= OUT_OFF + ATTN_SIZE) ? out + OUT_OFF
                                                              : nullptr;

    normalize_mask_kernel<<<1, 32>>>(mask);

    // Convert inputs/weights to fp16
    {
        int n8 = (int)(OUT_OFF / 8);                       // 8,388,608
        cvt_f32_f16_kernel<<<n8 / 256, 256>>>(X, xh_p, n8);
        int w8 = 3 * HID * HID / 8;
        cvt_f32_f16_kernel<<<(w8 + 255) / 256, 256>>>(Wqkv, wq_p, w8);
        int o8 = HID * HID / 8;
        cvt_f32_f16_kernel<<<(o8 + 255) / 256, 256>>>(Wo, wo_p, o8);
    }

    dim3 g1(3 * HID / BN, M_TOT / BM);   // (12, 1024)
    hmma_tn<true><<<g1, 256, GEMM_SMEM>>>(xh_p, wq_p, bqkv, qkv_p,
                                          M_TOT, 3 * HID, HID);

    attn_kernel<<<B_, 256, ATTN_SMEM>>>(qkv_p, attn_p, ctx_p);

    dim3 g2(HID / BN, M_TOT / BM);       // (4, 1024)
    hmma_tn<false><<<g2, 256, GEMM_SMEM>>>(ctx_p, wo_p, bo, out,
                                           M_TOT, HID, HID);
}

// round 9
// speedup vs baseline: 4.6115x; 1.1295x over previous
#include <cuda_runtime.h>
#include <cuda_fp16.h>
#include <math.h>
#include <stdint.h>

// Problem constants
#define B_    4096
#define N_    32
#define H_    8
#define HID   512
#define M_TOT (B_ * N_)                         // 131072
#define OUT_OFF ((size_t)M_TOT * HID)           // 67108864 floats
#define ATTN_SIZE ((size_t)B_ * H_ * N_ * N_)   // 33554432

// Scratch (device globals: allocation-guard safe)
__device__ __half g_qkvh[(size_t)M_TOT * 3 * HID];  // [B*N, 1536] fp16
__device__ __half g_ctxh[(size_t)M_TOT * HID];      // [B*N, 512] fp16
__device__ __half g_xh[(size_t)M_TOT * HID];        // fp16 X
__device__ __half g_wqh[(size_t)3 * HID * HID];     // fp16 Wqkv
__device__ __half g_woh[(size_t)HID * HID];         // fp16 Wo
__device__ unsigned g_mask_bits[32];

// ---------------------------------------------------------------------------
// Mask normalizer (dtype-agnostic: 1-byte bool vs 4-byte int/float)
// ---------------------------------------------------------------------------
__global__ void normalize_mask_kernel(const void* maskp) {
    int i = threadIdx.x;  // 0..31
    const unsigned char* m8 = (const unsigned char*)maskp;
    unsigned diag_ok = __ballot_sync(0xffffffffu, m8[i * 33] != 0);
    unsigned bits = 0;
    if (diag_ok == 0xffffffffu) {
        for (int j = 0; j < 32; j++)
            bits |= (unsigned)(m8[i * 32 + j] != 0) << j;
    } else {
        const int* m32 = (const int*)maskp;
        for (int j = 0; j < 32; j++)
            bits |= (unsigned)(m32[i * 32 + j] != 0) << j;
    }
    g_mask_bits[i] = bits;
}

// ---------------------------------------------------------------------------
// fp32 -> fp16 conversion, 8 floats per thread
// ---------------------------------------------------------------------------
__global__ void cvt_f32_f16_kernel(const float* __restrict__ in,
                                   __half* __restrict__ out, int n8) {
    int i = blockIdx.x * blockDim.x + threadIdx.x;
    if (i >= n8) return;
    float4 a = ((const float4*)in)[2 * i];
    float4 b = ((const float4*)in)[2 * i + 1];
    __half2 h[4];
    h[0] = __floats2half2_rn(a.x, a.y);
    h[1] = __floats2half2_rn(a.z, a.w);
    h[2] = __floats2half2_rn(b.x, b.y);
    h[3] = __floats2half2_rn(b.z, b.w);
    ((uint4*)out)[i] = *(uint4*)h;
}

// ---------------------------------------------------------------------------
// Shared PTX helpers
// ---------------------------------------------------------------------------
__device__ __forceinline__ void cp16(uint32_t dst, const void* src) {
    asm volatile("cp.async.cg.shared.global [%0], [%1], 16;\n"
                 :: "r"(dst), "l"(src));
}
__device__ __forceinline__ void ldsm_x4(uint32_t (&r)[4], uint32_t addr) {
    asm volatile("ldmatrix.sync.aligned.m8n8.x4.shared.b16 {%0,%1,%2,%3}, [%4];\n"
                 : "=r"(r[0]), "=r"(r[1]), "=r"(r[2]), "=r"(r[3]) : "r"(addr));
}
__device__ __forceinline__ void ldsm_x4_t(uint32_t (&r)[4], uint32_t addr) {
    asm volatile("ldmatrix.sync.aligned.m8n8.x4.trans.shared.b16 {%0,%1,%2,%3}, [%4];\n"
                 : "=r"(r[0]), "=r"(r[1]), "=r"(r[2]), "=r"(r[3]) : "r"(addr));
}
__device__ __forceinline__ void mma16816(float (&d)[4], const uint32_t (&a)[4],
                                         uint32_t b0, uint32_t b1) {
    asm volatile(
        "mma.sync.aligned.m16n8k16.row.col.f32.f16.f16.f32 "
        "{%0,%1,%2,%3}, {%4,%5,%6,%7}, {%8,%9}, {%0,%1,%2,%3};\n"
        : "+f"(d[0]), "+f"(d[1]), "+f"(d[2]), "+f"(d[3])
        : "r"(a[0]), "r"(a[1]), "r"(a[2]), "r"(a[3]), "r"(b0), "r"(b1));
}
__device__ __forceinline__ uint32_t packh2(float lo, float hi) {
    __half2 h = __floats2half2_rn(lo, hi);
    return *(uint32_t*)&h;
}

// ---------------------------------------------------------------------------
// FP16 tensor-core GEMM (TN): C[M,N] = A[M,K] @ W[N,K]^T + bias[N]
// 128x128x32 tile, 256 threads, 8 warps x (64x32), m16n8k16 + ldmatrix.x4.
// 3-stage cp.async pipeline, ONE __syncthreads per K-iter.
// ---------------------------------------------------------------------------
#define BM 128
#define BN 128
#define BK 32
#define SROW 40                              // fp16 units per smem row
#define TILE_H (BM * SROW)                   // 5120 fp16 per A tile
#define STAGE_H (2 * TILE_H)                 // A + B per stage
#define NSTAGE 3
#define GEMM_SMEM (NSTAGE * STAGE_H * 2)     // 61440 bytes

template <bool HOUT>
__global__ __launch_bounds__(256, 2) void hmma_tn(
    const __half* __restrict__ A, const __half* __restrict__ W,
    const float* __restrict__ bias, void* __restrict__ Cv,
    int M, int N, int K)
{
    extern __shared__ __half sh[];
    const int tid = threadIdx.x;
    const int bm = blockIdx.y * BM;
    const int bn = blockIdx.x * BN;

    const uint32_t sbase = (uint32_t)__cvta_generic_to_shared(sh);

    const int lrow = tid >> 1;                 // 0..127
    const int lk0 = (tid & 1) * 16;            // 0 or 16 (halves)
    const __half* Ag = A + (size_t)(bm + lrow) * K + lk0;
    const __half* Wg = W + (size_t)(bn + lrow) * K + lk0;

    auto issue = [&](int k0, int s) {
        uint32_t abuf = sbase + (uint32_t)(s * STAGE_H) * 2u;
        uint32_t bbuf = abuf + TILE_H * 2u;
        #pragma unroll
        for (int o = 0; o < 2; o++) {
            uint32_t soff = (uint32_t)(lrow * SROW + lk0 + o * 8) * 2u;
            cp16(abuf + soff, Ag + k0 + o * 8);
            cp16(bbuf + soff, Wg + k0 + o * 8);
        }
        asm volatile("cp.async.commit_group;\n");
    };

    const int warp = tid >> 5, lane = tid & 31;
    const int wm = (warp >> 2) * 64;
    const int wn = (warp & 3) * 32;
    const int qr = lane >> 2;
    const int qc = lane & 3;
    const int l15 = lane & 15;
    const int lhalf = lane >> 4;

    float acc[4][4][4];
    #pragma unroll
    for (int a = 0; a < 4; a++)
        #pragma unroll
        for (int b = 0; b < 4; b++)
            #pragma unroll
            for (int c = 0; c < 4; c++) acc[a][b][c] = 0.f;

    const int nIter = K / BK;
    issue(0, 0);
    issue(BK, 1);

    for (int it = 0; it < nIter; it++) {
        if (it + 1 < nIter) asm volatile("cp.async.wait_group 1;\n");
        else                asm volatile("cp.async.wait_group 0;\n");
        __syncthreads();
        if (it + 2 < nIter) issue((it + 2) * BK, (it + 2) % NSTAGE);

        const uint32_t abase = sbase + (uint32_t)((it % NSTAGE) * STAGE_H) * 2u;
        const uint32_t bbase = abase + TILE_H * 2u;

        #pragma unroll
        for (int ks = 0; ks < 2; ks++) {
            const int kcol = ks * 16 + lhalf * 8;
            uint32_t af[4][4];
            #pragma unroll
            for (int mt = 0; mt < 4; mt++)
                ldsm_x4(af[mt], abase +
                        (uint32_t)((wm + mt * 16 + l15) * SROW + kcol) * 2u);
            uint32_t bf[2][4];
            #pragma unroll
            for (int ng = 0; ng < 2; ng++)
                ldsm_x4(bf[ng], bbase +
                        (uint32_t)((wn + ng * 16 + l15) * SROW + kcol) * 2u);

            #pragma unroll
            for (int mt = 0; mt < 4; mt++)
                #pragma unroll
                for (int nt = 0; nt < 4; nt++)
                    mma16816(acc[mt][nt], af[mt],
                             bf[nt >> 1][(nt & 1)], bf[nt >> 1][(nt & 1) + 2]);
        }
    }

    #pragma unroll
    for (int nt = 0; nt < 4; nt++) {
        const int col = bn + wn + nt * 8 + qc * 2;
        const float2 bv = *(const float2*)(bias + col);
        #pragma unroll
        for (int mt = 0; mt < 4; mt++) {
            const int row = bm + wm + mt * 16 + qr;
            float2 v0 = { acc[mt][nt][0] + bv.x, acc[mt][nt][1] + bv.y };
            float2 v1 = { acc[mt][nt][2] + bv.x, acc[mt][nt][3] + bv.y };
            if (HOUT) {
                __half* C = (__half*)Cv;
                *(__half2*)(C + (size_t)row * N + col) =
                    __floats2half2_rn(v0.x, v0.y);
                *(__half2*)(C + (size_t)(row + 8) * N + col) =
                    __floats2half2_rn(v1.x, v1.y);
            } else {
                float* C = (float*)Cv;
                *(float2*)(C + (size_t)row * N + col) = v0;
                *(float2*)(C + (size_t)(row + 8) * N + col) = v1;
            }
        }
    }
}

// ---------------------------------------------------------------------------
// Tensor-core attention: one block per batch b, one warp per head h.
// QK^T and P*V on m16n8k16 mma; softmax fp32 in registers (shfl row-reduce).
// P stays in registers (S C-frag layout == PV A-frag layout). V via
// ldmatrix.trans. Per-warp smem: 2 tiles of 32x72 halves (K, and Q->V reuse).
// ---------------------------------------------------------------------------
#define ATS 72                              // halves per smem row
#define ATILE (32 * ATS)                    // 2304 halves per tile
#define AWARP (2 * ATILE)                   // per-warp halves
#define ATTN_SMEM (8 * AWARP * 2)           // 73728 bytes

__global__ __launch_bounds__(256) void attn_mma(
    const __half* __restrict__ qkv,
    float* __restrict__ attn_out,
    __half* __restrict__ ctx_out)
{
    extern __shared__ __half sha[];
    const int b = blockIdx.x;
    const int warp = threadIdx.x >> 5;    // head
    const int lane = threadIdx.x & 31;
    const int qr = lane >> 2, qc = lane & 3;
    const int l15 = lane & 15, lhalf = lane >> 4;

    __half* Qs = sha + warp * AWARP;      // later reused for V
    __half* Ks = Qs + ATILE;
    const uint32_t qsb = (uint32_t)__cvta_generic_to_shared(Qs);
    const uint32_t ksb = (uint32_t)__cvta_generic_to_shared(Ks);

    const __half* base = qkv + (size_t)b * 32 * 1536 + warp * 64;

    // ---- load Q, K tiles (one half2 per lane per row = 128B/row)
    #pragma unroll 4
    for (int r = 0; r < 32; r++) {
        ((__half2*)(Qs + r * ATS))[lane] =
            ((const __half2*)(base + (size_t)r * 1536))[lane];
        ((__half2*)(Ks + r * ATS))[lane] =
            ((const __half2*)(base + (size_t)r * 1536 + 512))[lane];
    }
    __syncwarp();

    // ---- Q A-frags [mt][kt], K B-frags [kt][ng]
    uint32_t qf[2][4][4];
    #pragma unroll
    for (int mt = 0; mt < 2; mt++)
        #pragma unroll
        for (int kt = 0; kt < 4; kt++)
            ldsm_x4(qf[mt][kt],
                    qsb + (uint32_t)((mt * 16 + l15) * ATS + kt * 16 + lhalf * 8) * 2u);
    uint32_t kf[4][2][4];
    #pragma unroll
    for (int kt = 0; kt < 4; kt++)
        #pragma unroll
        for (int ng = 0; ng < 2; ng++)
            ldsm_x4(kf[kt][ng],
                    ksb + (uint32_t)((ng * 16 + l15) * ATS + kt * 16 + lhalf * 8) * 2u);
    __syncwarp();

    // ---- load V into Q's buffer (frags already extracted)
    #pragma unroll 4
    for (int r = 0; r < 32; r++)
        ((__half2*)(Qs + r * ATS))[lane] =
            ((const __half2*)(base + (size_t)r * 1536 + 1024))[lane];

    // ---- S = QK^T
    float S[2][4][4];
    #pragma unroll
    for (int mt = 0; mt < 2; mt++)
        #pragma unroll
        for (int nt = 0; nt < 4; nt++)
            #pragma unroll
            for (int c = 0; c < 4; c++) S[mt][nt][c] = 0.f;
    #pragma unroll
    for (int kt = 0; kt < 4; kt++)
        #pragma unroll
        for (int mt = 0; mt < 2; mt++)
            #pragma unroll
            for (int nt = 0; nt < 4; nt++)
                mma16816(S[mt][nt], qf[mt][kt],
                         kf[kt][nt >> 1][(nt & 1)], kf[kt][nt >> 1][(nt & 1) + 2]);

    // ---- scale + mask + softmax (rows rlo=mt*16+qr, rhi=rlo+8)
    #pragma unroll
    for (int mt = 0; mt < 2; mt++) {
        const int rlo = mt * 16 + qr;
        const unsigned blo = g_mask_bits[rlo];
        const unsigned bhi = g_mask_bits[rlo + 8];
        float mlo = -1e30f, mhi = -1e30f;
        #pragma unroll
        for (int nt = 0; nt < 4; nt++) {
            const int n0 = nt * 8 + qc * 2;
            S[mt][nt][0] = ((blo >> n0) & 1u)       ? S[mt][nt][0] * 0.125f : -1e9f;
            S[mt][nt][1] = ((blo >> (n0 + 1)) & 1u) ? S[mt][nt][1] * 0.125f : -1e9f;
            S[mt][nt][2] = ((bhi >> n0) & 1u)       ? S[mt][nt][2] * 0.125f : -1e9f;
            S[mt][nt][3] = ((bhi >> (n0 + 1)) & 1u) ? S[mt][nt][3] * 0.125f : -1e9f;
            mlo = fmaxf(mlo, fmaxf(S[mt][nt][0], S[mt][nt][1]));
            mhi = fmaxf(mhi, fmaxf(S[mt][nt][2], S[mt][nt][3]));
        }
        mlo = fmaxf(mlo, __shfl_xor_sync(0xffffffffu, mlo, 1));
        mlo = fmaxf(mlo, __shfl_xor_sync(0xffffffffu, mlo, 2));
        mhi = fmaxf(mhi, __shfl_xor_sync(0xffffffffu, mhi, 1));
        mhi = fmaxf(mhi, __shfl_xor_sync(0xffffffffu, mhi, 2));
        float slo = 0.f, shi = 0.f;
        #pragma unroll
        for (int nt = 0; nt < 4; nt++) {
            S[mt][nt][0] = __expf(S[mt][nt][0] - mlo);
            S[mt][nt][1] = __expf(S[mt][nt][1] - mlo);
            S[mt][nt][2] = __expf(S[mt][nt][2] - mhi);
            S[mt][nt][3] = __expf(S[mt][nt][3] - mhi);
            slo += S[mt][nt][0] + S[mt][nt][1];
            shi += S[mt][nt][2] + S[mt][nt][3];
        }
        slo += __shfl_xor_sync(0xffffffffu, slo, 1);
        slo += __shfl_xor_sync(0xffffffffu, slo, 2);
        shi += __shfl_xor_sync(0xffffffffu, shi, 1);
        shi += __shfl_xor_sync(0xffffffffu, shi, 2);
        const float ilo = 1.f / slo, ihi = 1.f / shi;
        #pragma unroll
        for (int nt = 0; nt < 4; nt++) {
            S[mt][nt][0] *= ilo; S[mt][nt][1] *= ilo;
            S[mt][nt][2] *= ihi; S[mt][nt][3] *= ihi;
        }
    }

    // ---- attn output
    if (attn_out) {
        float* ao = attn_out + ((size_t)(b * 8 + warp) * 32) * 32;
        #pragma unroll
        for (int mt = 0; mt < 2; mt++) {
            const int rlo = mt * 16 + qr;
            #pragma unroll
            for (int nt = 0; nt < 4; nt++) {
                const int n0 = nt * 8 + qc * 2;
                *(float2*)(ao + rlo * 32 + n0) =
                    make_float2(S[mt][nt][0], S[mt][nt][1]);
                *(float2*)(ao + (rlo + 8) * 32 + n0) =
                    make_float2(S[mt][nt][2], S[mt][nt][3]);
            }
        }
    }

    // ---- P fp16 A-frags: S C-frag pairs ARE the A-frag layout
    uint32_t pf[2][2][4];   // [mt][kt2]
    #pragma unroll
    for (int mt = 0; mt < 2; mt++)
        #pragma unroll
        for (int k2 = 0; k2 < 2; k2++) {
            pf[mt][k2][0] = packh2(S[mt][2 * k2][0],     S[mt][2 * k2][1]);
            pf[mt][k2][1] = packh2(S[mt][2 * k2][2],     S[mt][2 * k2][3]);
            pf[mt][k2][2] = packh2(S[mt][2 * k2 + 1][0], S[mt][2 * k2 + 1][1]);
            pf[mt][k2][3] = packh2(S[mt][2 * k2 + 1][2], S[mt][2 * k2 + 1][3]);
        }
    __syncwarp();   // V tile fully written before ldsm

    // ---- ctx = P @ V, two d=32 phases (register cap)
    #pragma unroll
    for (int dn = 0; dn < 2; dn++) {
        uint32_t vf[2][2][4];   // [kt2][ng2] trans B-frags
        #pragma unroll
        for (int k2 = 0; k2 < 2; k2++)
            #pragma unroll
            for (int ng = 0; ng < 2; ng++)
                ldsm_x4_t(vf[k2][ng],
                          qsb + (uint32_t)((k2 * 16 + l15) * ATS +
                                           dn * 32 + ng * 16 + lhalf * 8) * 2u);
        float ctx[2][4][4];
        #pragma unroll
        for (int mt = 0; mt < 2; mt++)
            #pragma unroll
            for (int nt = 0; nt < 4; nt++)
                #pragma unroll
                for (int c = 0; c < 4; c++) ctx[mt][nt][c] = 0.f;
        #pragma unroll
        for (int k2 = 0; k2 < 2; k2++)
            #pragma unroll
            for (int mt = 0; mt < 2; mt++)
                #pragma unroll
                for (int nt = 0; nt < 4; nt++)
                    mma16816(ctx[mt][nt], pf[mt][k2],
                             vf[k2][nt >> 1][(nt & 1) * 2],
                             vf[k2][nt >> 1][(nt & 1) * 2 + 1]);
        // store fp16 ctx
        #pragma unroll
        for (int mt = 0; mt < 2; mt++) {
            const int rlo = mt * 16 + qr;
            #pragma unroll
            for (int nt = 0; nt < 4; nt++) {
                const int d0 = warp * 64 + dn * 32 + nt * 8 + qc * 2;
                __half* c0 = ctx_out + (size_t)(b * 32 + rlo) * HID + d0;
                __half* c1 = ctx_out + (size_t)(b * 32 + rlo + 8) * HID + d0;
                *(__half2*)c0 = __floats2half2_rn(ctx[mt][nt][0], ctx[mt][nt][1]);
                *(__half2*)c1 = __floats2half2_rn(ctx[mt][nt][2], ctx[mt][nt][3]);
            }
        }
    }
}

// ---------------------------------------------------------------------------
extern "C" void kernel_launch(void* const* d_in, const int* in_sizes, int n_in,
                              void* d_out, int out_size)
{
    const float* X    = (const float*)d_in[0];  // [B,N,HID]
    const void*  mask = d_in[1];                // [N,N]
    const float* Wqkv = (const float*)d_in[2];  // [1536,512]
    const float* bqkv = (const float*)d_in[3];  // [1536]
    const float* Wo   = (const float*)d_in[4];  // [512,512]
    const float* bo   = (const float*)d_in[5];  // [512]
    float* out = (float*)d_out;

    cudaFuncSetAttribute(attn_mma,
                         cudaFuncAttributeMaxDynamicSharedMemorySize, ATTN_SMEM);
    cudaFuncSetAttribute(hmma_tn<true>,
                         cudaFuncAttributeMaxDynamicSharedMemorySize, GEMM_SMEM);
    cudaFuncSetAttribute(hmma_tn<false>,
                         cudaFuncAttributeMaxDynamicSharedMemorySize, GEMM_SMEM);

    __half *qkv_p = nullptr, *ctx_p = nullptr, *xh_p = nullptr;
    __half *wq_p = nullptr, *wo_p = nullptr;
    cudaGetSymbolAddress((void**)&qkv_p, g_qkvh);
    cudaGetSymbolAddress((void**)&ctx_p, g_ctxh);
    cudaGetSymbolAddress((void**)&xh_p, g_xh);
    cudaGetSymbolAddress((void**)&wq_p, g_wqh);
    cudaGetSymbolAddress((void**)&wo_p, g_woh);

    float* attn_p = ((size_t)out_size >= OUT_OFF + ATTN_SIZE) ? out + OUT_OFF
                                                              : nullptr;

    normalize_mask_kernel<<<1, 32>>>(mask);

    // Convert inputs/weights to fp16
    {
        int n8 = (int)(OUT_OFF / 8);                       // 8,388,608
        cvt_f32_f16_kernel<<<n8 / 256, 256>>>(X, xh_p, n8);
        int w8 = 3 * HID * HID / 8;
        cvt_f32_f16_kernel<<<(w8 + 255) / 256, 256>>>(Wqkv, wq_p, w8);
        int o8 = HID * HID / 8;
        cvt_f32_f16_kernel<<<(o8 + 255) / 256, 256>>>(Wo, wo_p, o8);
    }

    dim3 g1(3 * HID / BN, M_TOT / BM);   // (12, 1024)
    hmma_tn<true><<<g1, 256, GEMM_SMEM>>>(xh_p, wq_p, bqkv, qkv_p,
                                          M_TOT, 3 * HID, HID);

    attn_mma<<<B_, 256, ATTN_SMEM>>>(qkv_p, attn_p, ctx_p);

    dim3 g2(HID / BN, M_TOT / BM);       // (4, 1024)
    hmma_tn<false><<<g2, 256, GEMM_SMEM>>>(ctx_p, wo_p, bo, out,
                                           M_TOT, HID, HID);
}